// round 14
// baseline (speedup 1.0000x reference)
#include <cuda_runtime.h>
#include <math_constants.h>

// ---------------------------------------------------------------------------
// EstimatorQNN, 2 qubits, 2 layers — SINGLE kernel, block-0 K producer +
// device-flag consumers (R14).
//
// Algebra: encoded state psi = (c0,s0)(x)(c1,s1); variational circuit = fixed
// 4x4 unitary U(weights); <Z0> = psi^T S psi, S = Re(U^H (Z(x)I) U).
// Double-angle collapse: result = 9 coefficients K over
// {1,cos(pi x0),sin(pi x0)} x {1,cos(pi x1),sin(pi x1)} -> 2 sincos + 8 FMA.
//
// Structure: ONLY block 0 (warp 0) derives K and publishes it via
// d_K + release flag. All other blocks: thread 0 spins on the flag (overlapped
// with that block's already-issued input loads), then __syncthreads. Waves 2+
// see the flag set — cost is one L2 read. The LAST block to finish resets
// flag and done-counter, so every launch (graph replay) starts from the same
// state. Streaming path = R3's proven shape: 4 samples/thread, 2x LDG.128 +
// 1x STG.128, flat 4096x256 grid (exactly 2^20 quads, no idle threads).
// ---------------------------------------------------------------------------

__device__ float d_K[9];          // the 9 double-angle coefficients
__device__ int   g_flag = 0;      // K-ready flag (reset by last block)
__device__ int   g_done = 0;      // completion counter (self-resetting)

struct Cx { float re, im; };

__device__ __forceinline__ Cx cmul(Cx a, Cx b) {
    Cx r; r.re = a.re * b.re - a.im * b.im; r.im = a.re * b.im + a.im * b.re; return r;
}
__device__ __forceinline__ Cx cadd(Cx a, Cx b) { Cx r; r.re = a.re + b.re; r.im = a.im + b.im; return r; }

__device__ __forceinline__ void apply_gate(Cx s[4], Cx m00, Cx m01, Cx m10, Cx m11, int q) {
    if (q == 0) {
#pragma unroll
        for (int j = 0; j < 2; j++) {
            Cx a = s[j], b = s[j + 2];
            s[j]     = cadd(cmul(m00, a), cmul(m01, b));
            s[j + 2] = cadd(cmul(m10, a), cmul(m11, b));
        }
    } else {
#pragma unroll
        for (int j = 0; j < 4; j += 2) {
            Cx a = s[j], b = s[j + 1];
            s[j]     = cadd(cmul(m00, a), cmul(m01, b));
            s[j + 1] = cadd(cmul(m10, a), cmul(m11, b));
        }
    }
}

struct KScratch {
    Cx U[4][4];       // U[k][b]
    float S[4][4];
};

// Warp-0-only K derivation (threads 0-3 simulate basis columns, 0-15 reduce
// S, thread 0 folds into d_K). Uses __syncwarp only — no block barrier.
__device__ void warp_build_K(const float4* __restrict__ w4, KScratch* sc) {
    int t = threadIdx.x;   // caller guarantees t < 32
    float wr[12];
    if (t < 4) {
        float4 w0 = w4[0], w1 = w4[1], w2 = w4[2];   // parallel float4 loads
        wr[0] = w0.x; wr[1]  = w0.y; wr[2]  = w0.z; wr[3]  = w0.w;
        wr[4] = w1.x; wr[5]  = w1.y; wr[6]  = w1.z; wr[7]  = w1.w;
        wr[8] = w2.x; wr[9]  = w2.y; wr[10] = w2.z; wr[11] = w2.w;
    }
    if (t < 4) {
        int b = t;
        Cx s[4];
#pragma unroll
        for (int k = 0; k < 4; k++) { s[k].re = (k == b) ? 1.0f : 0.0f; s[k].im = 0.0f; }
#pragma unroll
        for (int layer = 0; layer < 2; layer++) {
            int off = layer * 6;
#pragma unroll
            for (int q = 0; q < 2; q++) {
                float tx = wr[off + q * 3 + 0];
                float tz = wr[off + q * 3 + 1];
                float ty = wr[off + q * 3 + 2];
                float c, sn;
                c = __cosf(0.5f * tx); sn = __sinf(0.5f * tx);
                { Cx m00{c,0}, m01{0,-sn}, m10{0,-sn}, m11{c,0};
                  apply_gate(s, m00, m01, m10, m11, q); }
                c = __cosf(0.5f * tz); sn = __sinf(0.5f * tz);
                { Cx m00{c,-sn}, m01{0,0}, m10{0,0}, m11{c,sn};
                  apply_gate(s, m00, m01, m10, m11, q); }
                c = __cosf(0.5f * ty); sn = __sinf(0.5f * ty);
                { Cx m00{c,0}, m01{-sn,0}, m10{sn,0}, m11{c,0};
                  apply_gate(s, m00, m01, m10, m11, q); }
            }
            Cx tmp = s[2]; s[2] = s[3]; s[3] = tmp;  // CNOT(0->1): swap |10>,|11>
        }
#pragma unroll
        for (int k = 0; k < 4; k++) sc->U[k][b] = s[k];
    }
    __syncwarp();
    if (t < 16) {
        int i = t >> 2, j = t & 3;
        float acc = 0.0f;
#pragma unroll
        for (int k = 0; k < 4; k++) {
            float zk = (k < 2) ? 1.0f : -1.0f;
            acc += zk * (sc->U[k][i].re * sc->U[k][j].re + sc->U[k][i].im * sc->U[k][j].im);
        }
        sc->S[i][j] = acc;
    }
    __syncwarp();
    if (t == 0) {
        float c0 = sc->S[0][0], c1 = sc->S[1][1], c2 = sc->S[2][2], c3 = sc->S[3][3];
        float c4 = 2.0f * sc->S[0][1], c5 = 2.0f * sc->S[0][2], c6 = 2.0f * sc->S[0][3];
        float c7 = 2.0f * sc->S[1][2], c8 = 2.0f * sc->S[1][3], c9 = 2.0f * sc->S[2][3];
        d_K[0] = 0.25f * (c0 + c1 + c2 + c3);   // 1
        d_K[1] = 0.25f * (c0 - c1 + c2 - c3);   // C1
        d_K[2] = 0.25f * (c4 + c9);             // S1
        d_K[3] = 0.25f * (c0 + c1 - c2 - c3);   // C0
        d_K[4] = 0.25f * (c0 - c1 - c2 + c3);   // C0*C1
        d_K[5] = 0.25f * (c4 - c9);             // C0*S1
        d_K[6] = 0.25f * (c5 + c8);             // S0
        d_K[7] = 0.25f * (c5 - c8);             // S0*C1
        d_K[8] = 0.25f * (c6 + c7);             // S0*S1
        __threadfence();                        // publish d_K before flag
        *(volatile int*)&g_flag = 1;            // release
    }
}

__device__ __forceinline__ float eval_one(float x0, float x1, const float k[9]) {
    float S0, C0, S1, C1;
    __sincosf(CUDART_PI_F * x0, &S0, &C0);
    __sincosf(CUDART_PI_F * x1, &S1, &C1);
    float t1 = fmaf(k[2], S1, fmaf(k[1], C1, k[0]));
    float t2 = fmaf(k[5], S1, fmaf(k[4], C1, k[3]));
    float t3 = fmaf(k[8], S1, fmaf(k[7], C1, k[6]));
    return fmaf(S0, t3, fmaf(C0, t2, t1));
}

// Single fused kernel: block 0 produces K; others consume via flag.
__global__ void __launch_bounds__(256, 8) qnn_onekernel(
    const float4* __restrict__ in, float4* __restrict__ out,
    const float4* __restrict__ w4, int n_quads) {
    __shared__ KScratch sc;
    int t = threadIdx.x;
    int i = blockIdx.x * blockDim.x + t;
    bool valid = (i < n_quads);

    // Issue the long-latency input loads FIRST.
    float4 a, b;
    if (valid) {
        a = __ldcs(&in[2 * (size_t)i]);
        b = __ldcs(&in[2 * (size_t)i + 1]);
    }

    if (blockIdx.x == 0) {
        if (t < 32) warp_build_K(w4, &sc);
        __syncthreads();                 // d_K visible to whole block
    } else {
        if (t == 0) {
            while (*(volatile int*)&g_flag == 0) { __nanosleep(64); }
            __threadfence();             // acquire: order d_K reads after flag
        }
        __syncthreads();
    }

    float k[9];
#pragma unroll
    for (int j = 0; j < 9; j++) k[j] = d_K[j];

    if (valid) {
        float4 r;
        r.x = eval_one(a.x, a.y, k);
        r.y = eval_one(a.z, a.w, k);
        r.z = eval_one(b.x, b.y, k);
        r.w = eval_one(b.z, b.w, k);
        __stcs(&out[i], r);
    }

    // Reset protocol: last finishing block restores g_flag/g_done to 0 so
    // every launch (graph replay) starts from identical state.
    __syncthreads();
    if (t == 0) {
        int v = atomicAdd(&g_done, 1);
        if (v == (int)gridDim.x - 1) {
            g_flag = 0;
            atomicExch(&g_done, 0);
            __threadfence();
        }
    }
}

// Scalar tail for B % 4 != 0 (not hit for B = 4194304). Runs after main in
// stream order; d_K is valid and flag already reset (tail doesn't touch it).
__global__ void qnn_tail_kernel(const float2* __restrict__ in,
                                float* __restrict__ out, int start, int B) {
    float k[9];
#pragma unroll
    for (int j = 0; j < 9; j++) k[j] = d_K[j];
    int i = start + blockIdx.x * blockDim.x + threadIdx.x;
    if (i >= B) return;
    float2 x = in[i];
    out[i] = eval_one(x.x, x.y, k);
}

extern "C" void kernel_launch(void* const* d_in, const int* in_sizes, int n_in,
                              void* d_out, int out_size) {
    const float* inputs  = (const float*)d_in[0];   // [B,2]
    const float* weights = (const float*)d_in[1];   // [12]

    int B = in_sizes[0] / 2;            // 4194304
    int n_quads = B / 4;                // 1048576
    if (n_quads > 0) {
        int threads = 256;
        int blocks = (n_quads + threads - 1) / threads;   // 4096 (exact cover)
        qnn_onekernel<<<blocks, threads>>>((const float4*)inputs, (float4*)d_out,
                                           (const float4*)weights, n_quads);
    }
    int done = n_quads * 4;
    if (done < B) {
        int rem = B - done;
        qnn_tail_kernel<<<(rem + 127) / 128, 128>>>((const float2*)inputs,
                                                    (float*)d_out, done, B);
    }
}

// round 17
// speedup vs baseline: 1.1969x; 1.1969x over previous
#include <cuda_runtime.h>
#include <math_constants.h>

// ---------------------------------------------------------------------------
// EstimatorQNN, 2 qubits, 2 layers — single kernel, per-block K in SHARED,
// barrier wait filled with consumer work (R15/R16/R17).
//
// Algebra: encoded state psi = (c0,s0)(x)(c1,s1); variational circuit = fixed
// 4x4 unitary U(weights); <Z0> = psi^T S psi, S = Re(U^H (Z(x)I) U).
// Double-angle collapse: r = dot(K[9], {1,C0,S0}x{1,C1,S1}), C=cos(pi x),
// S=sin(pi x) -> per sample: 2 sincos + 8 FMA, K enters ONLY in the FMAs.
//
// Scheduling: while warp 0 derives K (weights -> gate chain -> sc.K), ALL
// threads do every K-independent op: 2x LDG.128 input loads AND all 8
// __sincosf. Producer (~800-950cy) and consumers (~750cy) arrive at the
// single __syncthreads nearly together -> exposed wait ~0. No global flags /
// atomics / epilogue. Deterministic, one launch.
// ---------------------------------------------------------------------------

struct Cx { float re, im; };

__device__ __forceinline__ Cx cmul(Cx a, Cx b) {
    Cx r; r.re = a.re * b.re - a.im * b.im; r.im = a.re * b.im + a.im * b.re; return r;
}
__device__ __forceinline__ Cx cadd(Cx a, Cx b) { Cx r; r.re = a.re + b.re; r.im = a.im + b.im; return r; }

__device__ __forceinline__ void apply_gate(Cx s[4], Cx m00, Cx m01, Cx m10, Cx m11, int q) {
    if (q == 0) {
#pragma unroll
        for (int j = 0; j < 2; j++) {
            Cx a = s[j], b = s[j + 2];
            s[j]     = cadd(cmul(m00, a), cmul(m01, b));
            s[j + 2] = cadd(cmul(m10, a), cmul(m11, b));
        }
    } else {
#pragma unroll
        for (int j = 0; j < 4; j += 2) {
            Cx a = s[j], b = s[j + 1];
            s[j]     = cadd(cmul(m00, a), cmul(m01, b));
            s[j + 1] = cadd(cmul(m10, a), cmul(m11, b));
        }
    }
}

struct KScratch {
    Cx U[4][4];       // U[k][b]
    float S[4][4];
    float K[9];
};

// Warp-0-only K derivation into sc->K. __syncwarp only; no block barrier.
__device__ __forceinline__ void warp_build_K(const float4* __restrict__ w4, KScratch* sc) {
    int t = threadIdx.x;   // caller guarantees t < 32
    if (t < 4) {
        float4 w0 = w4[0], w1 = w4[1], w2 = w4[2];   // parallel float4 loads
        float wr[12] = {w0.x, w0.y, w0.z, w0.w,
                        w1.x, w1.y, w1.z, w1.w,
                        w2.x, w2.y, w2.z, w2.w};

        int b = t;
        Cx s[4];
#pragma unroll
        for (int k = 0; k < 4; k++) { s[k].re = (k == b) ? 1.0f : 0.0f; s[k].im = 0.0f; }
#pragma unroll
        for (int layer = 0; layer < 2; layer++) {
            int off = layer * 6;
#pragma unroll
            for (int q = 0; q < 2; q++) {
                float tx = wr[off + q * 3 + 0];
                float tz = wr[off + q * 3 + 1];
                float ty = wr[off + q * 3 + 2];
                float c, sn;
                c = __cosf(0.5f * tx); sn = __sinf(0.5f * tx);
                { Cx m00{c,0}, m01{0,-sn}, m10{0,-sn}, m11{c,0};
                  apply_gate(s, m00, m01, m10, m11, q); }
                c = __cosf(0.5f * tz); sn = __sinf(0.5f * tz);
                { Cx m00{c,-sn}, m01{0,0}, m10{0,0}, m11{c,sn};
                  apply_gate(s, m00, m01, m10, m11, q); }
                c = __cosf(0.5f * ty); sn = __sinf(0.5f * ty);
                { Cx m00{c,0}, m01{-sn,0}, m10{sn,0}, m11{c,0};
                  apply_gate(s, m00, m01, m10, m11, q); }
            }
            Cx tmp = s[2]; s[2] = s[3]; s[3] = tmp;  // CNOT(0->1): swap |10>,|11>
        }
#pragma unroll
        for (int k = 0; k < 4; k++) sc->U[k][b] = s[k];
    }
    __syncwarp();
    if (t < 16) {
        int i = t >> 2, j = t & 3;
        float acc = 0.0f;
#pragma unroll
        for (int k = 0; k < 4; k++) {
            float zk = (k < 2) ? 1.0f : -1.0f;
            acc += zk * (sc->U[k][i].re * sc->U[k][j].re + sc->U[k][i].im * sc->U[k][j].im);
        }
        sc->S[i][j] = acc;
    }
    __syncwarp();
    if (t == 0) {
        float c0 = sc->S[0][0], c1 = sc->S[1][1], c2 = sc->S[2][2], c3 = sc->S[3][3];
        float c4 = 2.0f * sc->S[0][1], c5 = 2.0f * sc->S[0][2], c6 = 2.0f * sc->S[0][3];
        float c7 = 2.0f * sc->S[1][2], c8 = 2.0f * sc->S[1][3], c9 = 2.0f * sc->S[2][3];
        sc->K[0] = 0.25f * (c0 + c1 + c2 + c3);   // 1
        sc->K[1] = 0.25f * (c0 - c1 + c2 - c3);   // C1
        sc->K[2] = 0.25f * (c4 + c9);             // S1
        sc->K[3] = 0.25f * (c0 + c1 - c2 - c3);   // C0
        sc->K[4] = 0.25f * (c0 - c1 - c2 + c3);   // C0*C1
        sc->K[5] = 0.25f * (c4 - c9);             // C0*S1
        sc->K[6] = 0.25f * (c5 + c8);             // S0
        sc->K[7] = 0.25f * (c5 - c8);             // S0*C1
        sc->K[8] = 0.25f * (c6 + c7);             // S0*S1
    }
}

// K-dependent tail of the evaluation: 8 FMAs on precomputed sincos.
__device__ __forceinline__ float eval_fma(float c0, float s0, float c1, float s1,
                                          const float k[9]) {
    float t1 = fmaf(k[2], s1, fmaf(k[1], c1, k[0]));
    float t2 = fmaf(k[5], s1, fmaf(k[4], c1, k[3]));
    float t3 = fmaf(k[8], s1, fmaf(k[7], c1, k[6]));
    return fmaf(s0, t3, fmaf(c0, t2, t1));
}

// Single kernel: warp 0 builds K in shared while all threads load + sincos.
__global__ void __launch_bounds__(256) qnn_onekernel(
    const float4* __restrict__ in, float4* __restrict__ out,
    const float4* __restrict__ w4, int n_quads) {
    __shared__ KScratch sc;
    int t = threadIdx.x;
    int i = blockIdx.x * blockDim.x + t;
    bool valid = (i < n_quads);

    // 1) Input loads first (long-latency, K-independent).
    float4 a, b;
    if (valid) {
        a = __ldcs(&in[2 * (size_t)i]);
        b = __ldcs(&in[2 * (size_t)i + 1]);
    }

    // 2) Producer: warp 0 derives K into shared (runs while loads in flight
    //    block-wide; weight line is L2-resident after the first block).
    if (t < 32) warp_build_K(w4, &sc);

    // 3) Consumers (all threads incl. warp 0 after its chain): all 8 sincos —
    //    everything that doesn't need K. Only 16 floats live at the barrier.
    float c0a, s0a, c1a, s1a, c0b, s0b, c1b, s1b;
    float c0c, s0c, c1c, s1c, c0d, s0d, c1d, s1d;
    if (valid) {
        __sincosf(CUDART_PI_F * a.x, &s0a, &c0a);
        __sincosf(CUDART_PI_F * a.y, &s1a, &c1a);
        __sincosf(CUDART_PI_F * a.z, &s0b, &c0b);
        __sincosf(CUDART_PI_F * a.w, &s1b, &c1b);
        __sincosf(CUDART_PI_F * b.x, &s0c, &c0c);
        __sincosf(CUDART_PI_F * b.y, &s1c, &c1c);
        __sincosf(CUDART_PI_F * b.z, &s0d, &c0d);
        __sincosf(CUDART_PI_F * b.w, &s1d, &c1d);
    }

    // 4) Single barrier; arrival times balanced by construction.
    __syncthreads();

    float k[9];
#pragma unroll
    for (int j = 0; j < 9; j++) k[j] = sc.K[j];

    // 5) K-dependent tail: 8 FMAs per sample + store. Empty epilogue.
    if (valid) {
        float4 r;
        r.x = eval_fma(c0a, s0a, c1a, s1a, k);
        r.y = eval_fma(c0b, s0b, c1b, s1b, k);
        r.z = eval_fma(c0c, s0c, c1c, s1c, k);
        r.w = eval_fma(c0d, s0d, c1d, s1d, k);
        __stcs(&out[i], r);
    }
}

// Scalar tail for B % 4 != 0 (not hit for B = 4194304).
__global__ void qnn_tail_kernel(const float2* __restrict__ in,
                                float* __restrict__ out,
                                const float4* __restrict__ w4, int start, int B) {
    __shared__ KScratch sc;
    if (threadIdx.x < 32) warp_build_K(w4, &sc);
    __syncthreads();
    float k[9];
#pragma unroll
    for (int j = 0; j < 9; j++) k[j] = sc.K[j];
    int i = start + blockIdx.x * blockDim.x + threadIdx.x;
    if (i >= B) return;
    float2 x = in[i];
    float s0, c0, s1, c1;
    __sincosf(CUDART_PI_F * x.x, &s0, &c0);
    __sincosf(CUDART_PI_F * x.y, &s1, &c1);
    out[i] = eval_fma(c0, s0, c1, s1, k);
}

extern "C" void kernel_launch(void* const* d_in, const int* in_sizes, int n_in,
                              void* d_out, int out_size) {
    const float* inputs  = (const float*)d_in[0];   // [B,2]
    const float* weights = (const float*)d_in[1];   // [12]

    int B = in_sizes[0] / 2;            // 4194304
    int n_quads = B / 4;                // 1048576
    if (n_quads > 0) {
        int threads = 256;
        int blocks = (n_quads + threads - 1) / threads;   // 4096 (exact cover)
        qnn_onekernel<<<blocks, threads>>>((const float4*)inputs, (float4*)d_out,
                                           (const float4*)weights, n_quads);
    }
    int done = n_quads * 4;
    if (done < B) {
        int rem = B - done;
        qnn_tail_kernel<<<(rem + 127) / 128, 128>>>((const float2*)inputs,
                                                    (float*)d_out,
                                                    (const float4*)weights, done, B);
    }
}